// round 14
// baseline (speedup 1.0000x reference)
#include <cuda_runtime.h>
#include <cuda_bf16.h>
#include <math.h>

// ---------------------------------------------------------------------------
// SineLSTM v12 — v11 + (a) epilogue correction-term bugfix (full 3-term bf16
// restored), (b) per-warp producer-group barrier waits in the sequence phase
// (warp (mt,kh) depends only on CTAs [64kh, 64kh+64)).
// 128 CTAs x 512 thr (16 warps: 8 m-tiles x 2 k-halves).
// ---------------------------------------------------------------------------

#define NCTA 128
#define NTHR 512
#define HID  512
#define BAT  128

typedef unsigned int u32;

// fragment buffers: [mtile(8)][k16(32)][lane(32)] x uint4 (regs a0..a3, bf16x2)
__device__ __align__(16) uint4 g_h1h[2][8192];
__device__ __align__(16) uint4 g_h1l[2][8192];
__device__ __align__(16) uint4 g_h2h[2][8192];
__device__ __align__(16) uint4 g_h2l[2][8192];
__device__ __align__(16) float g_h2p[2][BAT * HID];   // plain [b][k] for projection
__device__ float g_xT[512 * BAT];                     // [t][b]
__device__ float g_xfeed[BAT];
__device__ unsigned g_arrive[NCTA];

// ---------------- helpers ---------------------------------------------------
__device__ __forceinline__ unsigned short bfbits(__nv_bfloat16 v) {
    return reinterpret_cast<unsigned short&>(v);
}
__device__ __forceinline__ void st16g(void* base, int word, int half, unsigned short v) {
    asm volatile("st.global.cg.u16 [%0], %1;"
                 :: "l"((char*)base + (size_t)word * 4 + half * 2), "h"(v) : "memory");
}
__device__ __forceinline__ void st_rel(unsigned* p, unsigned v) {
    asm volatile("st.release.gpu.u32 [%0], %1;" :: "l"(p), "r"(v) : "memory");
}
__device__ __forceinline__ unsigned ld_acq(unsigned* p) {
    unsigned v;
    asm volatile("ld.acquire.gpu.u32 %0, [%1];" : "=r"(v) : "l"(p) : "memory");
    return v;
}

__device__ __forceinline__ void mma16(float* c, uint4 a, u32 b0, u32 b1) {
    asm("mma.sync.aligned.m16n8k16.row.col.f32.bf16.bf16.f32 "
        "{%0,%1,%2,%3}, {%4,%5,%6,%7}, {%8,%9}, {%0,%1,%2,%3};"
        : "+f"(c[0]), "+f"(c[1]), "+f"(c[2]), "+f"(c[3])
        : "r"(a.x), "r"(a.y), "r"(a.z), "r"(a.w), "r"(b0), "r"(b1));
}

// ---------------- grid barrier pieces ---------------------------------------
__device__ __forceinline__ void barrier_arrive(unsigned barno) {
    __syncthreads();                       // all CTA work (incl. h stores) done
    if (threadIdx.x == 0) st_rel(&g_arrive[blockIdx.x], barno);
}
// full wait: all 128 flags (feedback phases)
__device__ __forceinline__ void barrier_wait_full(unsigned barno) {
    unsigned v;
    do {
        v = (threadIdx.x < NCTA) ? ld_acq(&g_arrive[threadIdx.x]) : barno;
    } while (__syncthreads_and(v >= barno) == 0);
}
// per-warp wait on producer group grp (64 flags, 2 per lane); warp-independent
__device__ __forceinline__ void warp_wait_group(int grp, unsigned barno, int lane) {
    unsigned* f = &g_arrive[(grp << 6) + (lane << 1)];
    for (;;) {
        unsigned a = ld_acq(f);
        unsigned b = ld_acq(f + 1);
        if (__all_sync(0xffffffffu, (a >= barno) && (b >= barno))) break;
    }
}

// ---------------- fused triple GEMM, half-K per warp ------------------------
// acc1 += h1 x Whh1^T ; acc2 += h1 x Wih2^T + h2 x Whh2^T over k-half kh.
__device__ __forceinline__ void mma_fused3(float (&a1M)[2][4], float (&a1C)[2][4],
                                           float (&a2M)[2][4], float (&a2C)[2][4],
                                           const uint4* __restrict__ wA,
                                           const uint4* __restrict__ wH,
                                           const uint4* __restrict__ wI,
                                           const uint4* __restrict__ g1h,
                                           const uint4* __restrict__ g1l,
                                           const uint4* __restrict__ g2h,
                                           const uint4* __restrict__ g2l,
                                           int lane, int mt, int kh) {
    const int base = mt * 1024 + kh * 512 + lane;
    const uint4* p1h = g1h + base;
    const uint4* p1l = g1l + base;
    const uint4* p2h = g2h + base;
    const uint4* p2l = g2l + base;
    uint4 f1h[2], f1l[2], f2h[2], f2l[2];
#pragma unroll
    for (int i = 0; i < 2; ++i) {
        f1h[i] = __ldcg(p1h + i * 32); f1l[i] = __ldcg(p1l + i * 32);
        f2h[i] = __ldcg(p2h + i * 32); f2l[i] = __ldcg(p2l + i * 32);
    }
#pragma unroll 4
    for (int k = 0; k < 16; ++k) {
        uint4 A1h = f1h[k & 1], A1l = f1l[k & 1];
        uint4 A2h = f2h[k & 1], A2l = f2l[k & 1];
        if (k < 14) {
            f1h[k & 1] = __ldcg(p1h + (k + 2) * 32);
            f1l[k & 1] = __ldcg(p1l + (k + 2) * 32);
            f2h[k & 1] = __ldcg(p2h + (k + 2) * 32);
            f2l[k & 1] = __ldcg(p2l + (k + 2) * 32);
        }
        const int wo = (kh * 16 + k) * 32 + lane;
        uint4 WAh = wA[wo], WAl = wA[1024 + wo];
        uint4 WHh = wH[wo], WHl = wH[1024 + wo];
        uint4 WIh = wI[wo], WIl = wI[1024 + wo];
        // layer 1: h1 x Whh1
        mma16(a1M[0], A1h, WAh.x, WAh.y);
        mma16(a1C[0], A1l, WAh.x, WAh.y);
        mma16(a1C[0], A1h, WAl.x, WAl.y);
        mma16(a1M[1], A1h, WAh.z, WAh.w);
        mma16(a1C[1], A1l, WAh.z, WAh.w);
        mma16(a1C[1], A1h, WAl.z, WAl.w);
        // layer 2: h1 x Wih2
        mma16(a2M[0], A1h, WIh.x, WIh.y);
        mma16(a2C[0], A1l, WIh.x, WIh.y);
        mma16(a2C[0], A1h, WIl.x, WIl.y);
        mma16(a2M[1], A1h, WIh.z, WIh.w);
        mma16(a2C[1], A1l, WIh.z, WIh.w);
        mma16(a2C[1], A1h, WIl.z, WIl.w);
        // layer 2: h2 x Whh2
        mma16(a2M[0], A2h, WHh.x, WHh.y);
        mma16(a2C[0], A2l, WHh.x, WHh.y);
        mma16(a2C[0], A2h, WHl.x, WHl.y);
        mma16(a2M[1], A2h, WHh.z, WHh.w);
        mma16(a2C[1], A2l, WHh.z, WHh.w);
        mma16(a2C[1], A2h, WHl.z, WHl.w);
    }
}

// ---------------- reset / transpose ----------------------------------------
__global__ void reset_kernel(const float* __restrict__ x, int T) {
    int idx = blockIdx.x * blockDim.x + threadIdx.x;
    uint4 z4 = make_uint4(0, 0, 0, 0);
    if (idx < 16384) {
        ((uint4*)g_h1h)[idx] = z4; ((uint4*)g_h1l)[idx] = z4;
        ((uint4*)g_h2h)[idx] = z4; ((uint4*)g_h2l)[idx] = z4;
    }
    if (idx < 2 * BAT * HID) ((float*)g_h2p)[idx] = 0.f;
    if (idx < BAT * T) {
        int b = idx / T, t = idx - b * T;
        g_xT[t * BAT + b] = x[idx];
    }
    if (idx < NCTA) g_arrive[idx] = 0;
    if (idx < BAT)  g_xfeed[idx] = 0.f;
}

// ---------------- main persistent kernel -----------------------------------
__global__ void __launch_bounds__(NTHR, 1)
lstm_main(const float* __restrict__ Wih1, const float* __restrict__ Whh1,
          const float* __restrict__ bih1, const float* __restrict__ bhh1,
          const float* __restrict__ Wih2, const float* __restrict__ Whh2,
          const float* __restrict__ bih2, const float* __restrict__ bhh2,
          const float* __restrict__ Wout, const float* __restrict__ bout,
          float* __restrict__ out, int T, int F) {
    extern __shared__ float sm[];
    __shared__ float s_red[16];
    __shared__ float4 s_kx[8][32][4];     // partial-sum exchange: 16 KB

    const int tid  = threadIdx.x;
    const int lane = tid & 31;
    const int wid  = tid >> 5;            // warp 0..15
    const int mt   = wid & 7;             // m-tile (16 batches)
    const int kh   = wid >> 3;            // k-half: 0 = k16 [0,16), 1 = [16,32)
    const int bid  = blockIdx.x;
    const int r    = lane >> 2;           // fragment row 0..7
    const int u    = lane & 3;            // hidden unit (of CTA's 4)

    // ---- one-time: split weights into SMEM bf16 fragment layout -----------
    {
        const float* Ws[3] = { Whh1, Whh2, Wih2 };
        for (int idx = tid; idx < 8192; idx += NTHR) {
            int n = idx >> 9, k = idx & 511;
            int uu = (n & 7) >> 1, g = (n & 1) + 2 * (n >> 3);
            int row = g * HID + bid * 4 + uu;
            int k16 = k >> 4, kc = k & 15;
            int ln  = (n & 7) * 4 + ((kc & 7) >> 1);
            int word = (k16 * 32 + ln) * 4 + (n >> 3) * 2 + (kc >> 3);
            int half = kc & 1;
#pragma unroll
            for (int m = 0; m < 3; ++m) {
                float w = __ldg(Ws[m] + row * HID + k);
                __nv_bfloat16 bh = __float2bfloat16(w);
                __nv_bfloat16 bl = __float2bfloat16(w - __bfloat162float(bh));
                ((unsigned short*)(sm + m * 8192))[word * 2 + half]        = bfbits(bh);
                ((unsigned short*)(sm + m * 8192 + 4096))[word * 2 + half] = bfbits(bl);
            }
        }
    }
    float b1g[4], b2g[4], wxg[4];
#pragma unroll
    for (int g = 0; g < 4; ++g) {
        int row = g * HID + bid * 4 + u;
        b1g[g] = __ldg(bih1 + row) + __ldg(bhh1 + row);
        b2g[g] = __ldg(bih2 + row) + __ldg(bhh2 + row);
        wxg[g] = __ldg(Wih1 + row);
    }
    const float bo_out = __ldg(bout);
    __syncthreads();

    const uint4* wA = (const uint4*)sm;              // Whh1 (lo at +1024)
    const uint4* wH = (const uint4*)(sm + 8192);     // Whh2
    const uint4* wI = (const uint4*)(sm + 16384);    // Wih2

    const int b0 = mt * 16 + r;
    const int b1 = b0 + 8;
    const int kk = 4 * bid + u;
    const int q16 = bid >> 2;
    const int kc  = 4 * (bid & 3) + u;
    const int Ls  = r * 4 + ((kc & 7) >> 1);
    const int rb  = (kc >= 8) ? 2 : 0;
    const int hf  = kc & 1;
    const int fidx = ((mt * 32 + q16) * 32 + Ls) * 4 + rb;

    const int TF = T + F;
    float c1[2] = {0.f, 0.f}, c2[2] = {0.f, 0.f};
    int p = 0, q = 0;
    unsigned barno = 0;
    float a1M[2][4], a1C[2][4], a2M[2][4], a2C[2][4];

#define ZEROACC()                                                              \
    do {                                                                       \
        _Pragma("unroll")                                                      \
        for (int n = 0; n < 2; ++n)                                            \
            _Pragma("unroll")                                                  \
            for (int i = 0; i < 4; ++i)                                        \
                { a1M[n][i]=0.f; a1C[n][i]=0.f; a2M[n][i]=0.f; a2C[n][i]=0.f; } \
    } while (0)

// symmetric exchange: kh0 publishes layer-1 full partials, kh1 publishes
// layer-2 full; kh1 folds layer-1 into a1M, kh0 folds layer-2 into a2M.
// Executing warp's OWN correction (a1C / a2C) stays in regs and is added in
// the epilogues (v11 bug: it was dropped).
#define EXCHANGE()                                                             \
    do {                                                                       \
        if (kh == 0) {                                                         \
            s_kx[mt][lane][0] = make_float4(a1M[0][0]+a1C[0][0], a1M[0][1]+a1C[0][1], \
                                            a1M[0][2]+a1C[0][2], a1M[0][3]+a1C[0][3]); \
            s_kx[mt][lane][1] = make_float4(a1M[1][0]+a1C[1][0], a1M[1][1]+a1C[1][1], \
                                            a1M[1][2]+a1C[1][2], a1M[1][3]+a1C[1][3]); \
        } else {                                                               \
            s_kx[mt][lane][2] = make_float4(a2M[0][0]+a2C[0][0], a2M[0][1]+a2C[0][1], \
                                            a2M[0][2]+a2C[0][2], a2M[0][3]+a2C[0][3]); \
            s_kx[mt][lane][3] = make_float4(a2M[1][0]+a2C[1][0], a2M[1][1]+a2C[1][1], \
                                            a2M[1][2]+a2C[1][2], a2M[1][3]+a2C[1][3]); \
        }                                                                      \
        __syncthreads();                                                       \
        if (kh == 1) {                                                         \
            float4 e;                                                          \
            e = s_kx[mt][lane][0];                                             \
            a1M[0][0]+=e.x; a1M[0][1]+=e.y; a1M[0][2]+=e.z; a1M[0][3]+=e.w;    \
            e = s_kx[mt][lane][1];                                             \
            a1M[1][0]+=e.x; a1M[1][1]+=e.y; a1M[1][2]+=e.z; a1M[1][3]+=e.w;    \
        } else {                                                               \
            float4 e;                                                          \
            e = s_kx[mt][lane][2];                                             \
            a2M[0][0]+=e.x; a2M[0][1]+=e.y; a2M[0][2]+=e.z; a2M[0][3]+=e.w;    \
            e = s_kx[mt][lane][3];                                             \
            a2M[1][0]+=e.x; a2M[1][1]+=e.y; a2M[1][2]+=e.z; a2M[1][3]+=e.w;    \
        }                                                                      \
    } while (0)

#define PROJECT(bufq, tpos, feed)                                              \
    do {                                                                       \
        float part = __ldcg(g_h2p[bufq] + bid * HID + tid) * __ldg(Wout + tid);\
        _Pragma("unroll")                                                      \
        for (int sh = 16; sh; sh >>= 1)                                        \
            part += __shfl_xor_sync(0xffffffffu, part, sh);                    \
        if (lane == 0) s_red[wid] = part;                                      \
        __syncthreads();                                                       \
        if (tid == 0) {                                                        \
            float o = bo_out;                                                  \
            _Pragma("unroll")                                                  \
            for (int wq = 0; wq < 16; ++wq) o += s_red[wq];                    \
            out[bid * TF + (tpos)] = o;                                        \
            if (feed) __stcg(g_xfeed + bid, o);                                \
        }                                                                      \
        __syncthreads();                                                       \
    } while (0)

// layer-1 cell update (kh==1 warps): a1M folded full other-half + own main;
// a1C = own correction (now correctly added).
#define EPILOGUE1(xq0v, xq1v)                                                  \
    do {                                                                       \
        float xq[2] = { xq0v, xq1v };                                          \
        _Pragma("unroll")                                                      \
        for (int j = 0; j < 2; ++j) {                                          \
            float gi = a1M[0][j*2]   + a1C[0][j*2]   + b1g[0] + wxg[0] * xq[j];\
            float gf = a1M[0][j*2+1] + a1C[0][j*2+1] + b1g[1] + wxg[1] * xq[j];\
            float gg = a1M[1][j*2]   + a1C[1][j*2]   + b1g[2] + wxg[2] * xq[j];\
            float go = a1M[1][j*2+1] + a1C[1][j*2+1] + b1g[3] + wxg[3] * xq[j];\
            float ii = 1.f / (1.f + expf(-gi));                                \
            float ff = 1.f / (1.f + expf(-gf));                                \
            float g_ = tanhf(gg);                                              \
            float oo = 1.f / (1.f + expf(-go));                                \
            c1[j] = ff * c1[j] + ii * g_;                                      \
            float hv = oo * tanhf(c1[j]);                                      \
            __nv_bfloat16 bh = __float2bfloat16(hv);                           \
            __nv_bfloat16 bl = __float2bfloat16(hv - __bfloat162float(bh));    \
            st16g(g_h1h[p ^ 1], fidx + j, hf, bfbits(bh));                     \
            st16g(g_h1l[p ^ 1], fidx + j, hf, bfbits(bl));                     \
        }                                                                      \
    } while (0)

// layer-2 cell update (kh==0 warps): a2M folded full + own a2C correction.
#define EPILOGUE2()                                                            \
    do {                                                                       \
        _Pragma("unroll")                                                      \
        for (int j = 0; j < 2; ++j) {                                          \
            float gi = a2M[0][j*2]   + a2C[0][j*2]   + b2g[0];                 \
            float gf = a2M[0][j*2+1] + a2C[0][j*2+1] + b2g[1];                 \
            float gg = a2M[1][j*2]   + a2C[1][j*2]   + b2g[2];                 \
            float go = a2M[1][j*2+1] + a2C[1][j*2+1] + b2g[3];                 \
            float ii = 1.f / (1.f + expf(-gi));                                \
            float ff = 1.f / (1.f + expf(-gf));                                \
            float g_ = tanhf(gg);                                              \
            float oo = 1.f / (1.f + expf(-go));                                \
            c2[j] = ff * c2[j] + ii * g_;                                      \
            float hv = oo * tanhf(c2[j]);                                      \
            __nv_bfloat16 bh = __float2bfloat16(hv);                           \
            __nv_bfloat16 bl = __float2bfloat16(hv - __bfloat162float(bh));    \
            st16g(g_h2h[q ^ 1], fidx + j, hf, bfbits(bh));                     \
            st16g(g_h2l[q ^ 1], fidx + j, hf, bfbits(bl));                     \
            __stcg(g_h2p[q ^ 1] + (j ? b1 : b0) * HID + kk, hv);               \
        }                                                                      \
    } while (0)

    // ================= sequence supersteps s = 0..T-1 ======================
    // superstep s: h1(s) [kh1 epilogue] and h2(s-1) [kh0 epilogue];
    // out(s-2) projected in the barrier shadow; per-warp group waits.
    for (int s = 0; s < T; ++s) {
        const float* xsrc = g_xT + s * BAT;
        float xq0 = __ldcg(xsrc + b0);           // hidden under the GEMM
        float xq1 = __ldcg(xsrc + b1);

        ZEROACC();
        mma_fused3(a1M, a1C, a2M, a2C, wA, wH, wI,
                   g_h1h[p], g_h1l[p], g_h2h[q], g_h2l[q], lane, mt, kh);
        EXCHANGE();
        if (kh == 1) EPILOGUE1(xq0, xq1);
        else if (s > 0) EPILOGUE2();             // h2(s-1); zero at s=0
        barrier_arrive(++barno);
        if (s >= 2) PROJECT(q, s - 2, false);    // shadow work
        warp_wait_group(kh, barno, lane);        // only this warp's producers
        p ^= 1; q ^= 1;
    }

    // ================= feedback supersteps s = T..TF-1 =====================
    for (int s = T; s < TF; ++s) {
        ZEROACC();
        mma_fused3(a1M, a1C, a2M, a2C, wA, wH, wI,
                   g_h1h[p], g_h1l[p], g_h2h[q], g_h2l[q], lane, mt, kh);
        EXCHANGE();
        if (kh == 0) EPILOGUE2();                // h2(s-1)
        barrier_arrive(++barno);
        if (s == T) PROJECT(q, T - 2, false);    // straggler out(T-2), in shadow
        barrier_wait_full(barno);                // h2(s-1) visible
        PROJECT(q ^ 1, s - 1, true);             // out(s-1) -> xfeed = x(s)
        barrier_arrive(++barno);
        barrier_wait_full(barno);                // xfeed visible
        if (kh == 1) {
            EPILOGUE1(__ldcg(g_xfeed + b0), __ldcg(g_xfeed + b1));
        }
        barrier_arrive(++barno);
        barrier_wait_full(barno);                // h1(s) visible
        p ^= 1; q ^= 1;
    }

    // ================= final superstep: layer 2 only for h2(TF-1) ==========
    ZEROACC();
    mma_fused3(a1M, a1C, a2M, a2C, wA, wH, wI,
               g_h1h[p], g_h1l[p], g_h2h[q], g_h2l[q], lane, mt, kh);
    EXCHANGE();
    if (kh == 0) EPILOGUE2();                    // h2(TF-1)
    barrier_arrive(++barno);
    barrier_wait_full(barno);
    PROJECT(q ^ 1, TF - 1, false);               // emit out(TF-1)

#undef ZEROACC
#undef EXCHANGE
#undef PROJECT
#undef EPILOGUE1
#undef EPILOGUE2
}

// ---------------------------------------------------------------------------
extern "C" void kernel_launch(void* const* d_in, const int* in_sizes, int n_in,
                              void* d_out, int out_size) {
    const float* x    = (const float*)d_in[0];
    const float* Wih1 = (const float*)d_in[2];
    const float* Whh1 = (const float*)d_in[3];
    const float* bih1 = (const float*)d_in[4];
    const float* bhh1 = (const float*)d_in[5];
    const float* Wih2 = (const float*)d_in[6];
    const float* Whh2 = (const float*)d_in[7];
    const float* bih2 = (const float*)d_in[8];
    const float* bhh2 = (const float*)d_in[9];
    const float* Wout = (const float*)d_in[10];
    const float* bout = (const float*)d_in[11];

    int T  = in_sizes[0] / BAT;       // 512
    int TF = out_size / BAT;          // 576
    int F  = TF - T;                  // 64

    const int smem = 24576 * 4;       // 98304 B dynamic (weights)

    cudaFuncSetAttribute(lstm_main, cudaFuncAttributeMaxDynamicSharedMemorySize, smem);

    reset_kernel<<<512, 256>>>(x, T);
    lstm_main<<<NCTA, NTHR, smem>>>(Wih1, Whh1, bih1, bhh1,
                                    Wih2, Whh2, bih2, bhh2,
                                    Wout, bout, (float*)d_out, T, F);
}

// round 15
// speedup vs baseline: 1.2773x; 1.2773x over previous
#include <cuda_runtime.h>
#include <cuda_bf16.h>
#include <math.h>

// ---------------------------------------------------------------------------
// SineLSTM v13 — v11 structure (split grid barrier with all-poll-all
// syncthreads_and wait, PROJECT in the barrier shadow, symmetric kh epilogue
// split) + the v12 correction-term accuracy fix. The v12 per-warp poll loop
// (poll-storm regression) is reverted.
// 128 CTAs x 512 thr (16 warps: 8 m-tiles x 2 k-halves).
// ---------------------------------------------------------------------------

#define NCTA 128
#define NTHR 512
#define HID  512
#define BAT  128

typedef unsigned int u32;

// fragment buffers: [mtile(8)][k16(32)][lane(32)] x uint4 (regs a0..a3, bf16x2)
__device__ __align__(16) uint4 g_h1h[2][8192];
__device__ __align__(16) uint4 g_h1l[2][8192];
__device__ __align__(16) uint4 g_h2h[2][8192];
__device__ __align__(16) uint4 g_h2l[2][8192];
__device__ __align__(16) float g_h2p[2][BAT * HID];   // plain [b][k] for projection
__device__ float g_xT[512 * BAT];                     // [t][b]
__device__ float g_xfeed[BAT];
__device__ unsigned g_arrive[NCTA];

// ---------------- helpers ---------------------------------------------------
__device__ __forceinline__ unsigned short bfbits(__nv_bfloat16 v) {
    return reinterpret_cast<unsigned short&>(v);
}
__device__ __forceinline__ void st16g(void* base, int word, int half, unsigned short v) {
    asm volatile("st.global.cg.u16 [%0], %1;"
                 :: "l"((char*)base + (size_t)word * 4 + half * 2), "h"(v) : "memory");
}
__device__ __forceinline__ void st_rel(unsigned* p, unsigned v) {
    asm volatile("st.release.gpu.u32 [%0], %1;" :: "l"(p), "r"(v) : "memory");
}
__device__ __forceinline__ unsigned ld_acq(unsigned* p) {
    unsigned v;
    asm volatile("ld.acquire.gpu.u32 %0, [%1];" : "=r"(v) : "l"(p) : "memory");
    return v;
}

__device__ __forceinline__ void mma16(float* c, uint4 a, u32 b0, u32 b1) {
    asm("mma.sync.aligned.m16n8k16.row.col.f32.bf16.bf16.f32 "
        "{%0,%1,%2,%3}, {%4,%5,%6,%7}, {%8,%9}, {%0,%1,%2,%3};"
        : "+f"(c[0]), "+f"(c[1]), "+f"(c[2]), "+f"(c[3])
        : "r"(a.x), "r"(a.y), "r"(a.z), "r"(a.w), "r"(b0), "r"(b1));
}

// ---------------- split grid barrier (all-poll-all, one hop) ----------------
__device__ __forceinline__ void barrier_arrive(unsigned barno) {
    __syncthreads();                       // all CTA work (incl. h stores) done
    if (threadIdx.x == 0) st_rel(&g_arrive[blockIdx.x], barno);
}
__device__ __forceinline__ void barrier_wait(unsigned barno) {
    unsigned v;
    do {
        v = (threadIdx.x < NCTA) ? ld_acq(&g_arrive[threadIdx.x]) : barno;
    } while (__syncthreads_and(v >= barno) == 0);
}

// ---------------- fused triple GEMM, half-K per warp ------------------------
// acc1 += h1 x Whh1^T ; acc2 += h1 x Wih2^T + h2 x Whh2^T over k-half kh.
__device__ __forceinline__ void mma_fused3(float (&a1M)[2][4], float (&a1C)[2][4],
                                           float (&a2M)[2][4], float (&a2C)[2][4],
                                           const uint4* __restrict__ wA,
                                           const uint4* __restrict__ wH,
                                           const uint4* __restrict__ wI,
                                           const uint4* __restrict__ g1h,
                                           const uint4* __restrict__ g1l,
                                           const uint4* __restrict__ g2h,
                                           const uint4* __restrict__ g2l,
                                           int lane, int mt, int kh) {
    const int base = mt * 1024 + kh * 512 + lane;
    const uint4* p1h = g1h + base;
    const uint4* p1l = g1l + base;
    const uint4* p2h = g2h + base;
    const uint4* p2l = g2l + base;
    uint4 f1h[2], f1l[2], f2h[2], f2l[2];
#pragma unroll
    for (int i = 0; i < 2; ++i) {
        f1h[i] = __ldcg(p1h + i * 32); f1l[i] = __ldcg(p1l + i * 32);
        f2h[i] = __ldcg(p2h + i * 32); f2l[i] = __ldcg(p2l + i * 32);
    }
#pragma unroll 4
    for (int k = 0; k < 16; ++k) {
        uint4 A1h = f1h[k & 1], A1l = f1l[k & 1];
        uint4 A2h = f2h[k & 1], A2l = f2l[k & 1];
        if (k < 14) {
            f1h[k & 1] = __ldcg(p1h + (k + 2) * 32);
            f1l[k & 1] = __ldcg(p1l + (k + 2) * 32);
            f2h[k & 1] = __ldcg(p2h + (k + 2) * 32);
            f2l[k & 1] = __ldcg(p2l + (k + 2) * 32);
        }
        const int wo = (kh * 16 + k) * 32 + lane;
        uint4 WAh = wA[wo], WAl = wA[1024 + wo];
        uint4 WHh = wH[wo], WHl = wH[1024 + wo];
        uint4 WIh = wI[wo], WIl = wI[1024 + wo];
        // layer 1: h1 x Whh1
        mma16(a1M[0], A1h, WAh.x, WAh.y);
        mma16(a1C[0], A1l, WAh.x, WAh.y);
        mma16(a1C[0], A1h, WAl.x, WAl.y);
        mma16(a1M[1], A1h, WAh.z, WAh.w);
        mma16(a1C[1], A1l, WAh.z, WAh.w);
        mma16(a1C[1], A1h, WAl.z, WAl.w);
        // layer 2: h1 x Wih2
        mma16(a2M[0], A1h, WIh.x, WIh.y);
        mma16(a2C[0], A1l, WIh.x, WIh.y);
        mma16(a2C[0], A1h, WIl.x, WIl.y);
        mma16(a2M[1], A1h, WIh.z, WIh.w);
        mma16(a2C[1], A1l, WIh.z, WIh.w);
        mma16(a2C[1], A1h, WIl.z, WIl.w);
        // layer 2: h2 x Whh2
        mma16(a2M[0], A2h, WHh.x, WHh.y);
        mma16(a2C[0], A2l, WHh.x, WHh.y);
        mma16(a2C[0], A2h, WHl.x, WHl.y);
        mma16(a2M[1], A2h, WHh.z, WHh.w);
        mma16(a2C[1], A2l, WHh.z, WHh.w);
        mma16(a2C[1], A2h, WHl.z, WHl.w);
    }
}

// ---------------- reset / transpose ----------------------------------------
__global__ void reset_kernel(const float* __restrict__ x, int T) {
    int idx = blockIdx.x * blockDim.x + threadIdx.x;
    uint4 z4 = make_uint4(0, 0, 0, 0);
    if (idx < 16384) {
        ((uint4*)g_h1h)[idx] = z4; ((uint4*)g_h1l)[idx] = z4;
        ((uint4*)g_h2h)[idx] = z4; ((uint4*)g_h2l)[idx] = z4;
    }
    if (idx < 2 * BAT * HID) ((float*)g_h2p)[idx] = 0.f;
    if (idx < BAT * T) {
        int b = idx / T, t = idx - b * T;
        g_xT[t * BAT + b] = x[idx];
    }
    if (idx < NCTA) g_arrive[idx] = 0;
    if (idx < BAT)  g_xfeed[idx] = 0.f;
}

// ---------------- main persistent kernel -----------------------------------
__global__ void __launch_bounds__(NTHR, 1)
lstm_main(const float* __restrict__ Wih1, const float* __restrict__ Whh1,
          const float* __restrict__ bih1, const float* __restrict__ bhh1,
          const float* __restrict__ Wih2, const float* __restrict__ Whh2,
          const float* __restrict__ bih2, const float* __restrict__ bhh2,
          const float* __restrict__ Wout, const float* __restrict__ bout,
          float* __restrict__ out, int T, int F) {
    extern __shared__ float sm[];
    __shared__ float s_red[16];
    __shared__ float4 s_kx[8][32][4];     // partial-sum exchange: 16 KB

    const int tid  = threadIdx.x;
    const int lane = tid & 31;
    const int wid  = tid >> 5;            // warp 0..15
    const int mt   = wid & 7;             // m-tile (16 batches)
    const int kh   = wid >> 3;            // k-half: 0 = k16 [0,16), 1 = [16,32)
    const int bid  = blockIdx.x;
    const int r    = lane >> 2;           // fragment row 0..7
    const int u    = lane & 3;            // hidden unit (of CTA's 4)

    // ---- one-time: split weights into SMEM bf16 fragment layout -----------
    {
        const float* Ws[3] = { Whh1, Whh2, Wih2 };
        for (int idx = tid; idx < 8192; idx += NTHR) {
            int n = idx >> 9, k = idx & 511;
            int uu = (n & 7) >> 1, g = (n & 1) + 2 * (n >> 3);
            int row = g * HID + bid * 4 + uu;
            int k16 = k >> 4, kc = k & 15;
            int ln  = (n & 7) * 4 + ((kc & 7) >> 1);
            int word = (k16 * 32 + ln) * 4 + (n >> 3) * 2 + (kc >> 3);
            int half = kc & 1;
#pragma unroll
            for (int m = 0; m < 3; ++m) {
                float w = __ldg(Ws[m] + row * HID + k);
                __nv_bfloat16 bh = __float2bfloat16(w);
                __nv_bfloat16 bl = __float2bfloat16(w - __bfloat162float(bh));
                ((unsigned short*)(sm + m * 8192))[word * 2 + half]        = bfbits(bh);
                ((unsigned short*)(sm + m * 8192 + 4096))[word * 2 + half] = bfbits(bl);
            }
        }
    }
    float b1g[4], b2g[4], wxg[4];
#pragma unroll
    for (int g = 0; g < 4; ++g) {
        int row = g * HID + bid * 4 + u;
        b1g[g] = __ldg(bih1 + row) + __ldg(bhh1 + row);
        b2g[g] = __ldg(bih2 + row) + __ldg(bhh2 + row);
        wxg[g] = __ldg(Wih1 + row);
    }
    const float bo_out = __ldg(bout);
    __syncthreads();

    const uint4* wA = (const uint4*)sm;              // Whh1 (lo at +1024)
    const uint4* wH = (const uint4*)(sm + 8192);     // Whh2
    const uint4* wI = (const uint4*)(sm + 16384);    // Wih2

    const int b0 = mt * 16 + r;
    const int b1 = b0 + 8;
    const int kk = 4 * bid + u;
    const int q16 = bid >> 2;
    const int kc  = 4 * (bid & 3) + u;
    const int Ls  = r * 4 + ((kc & 7) >> 1);
    const int rb  = (kc >= 8) ? 2 : 0;
    const int hf  = kc & 1;
    const int fidx = ((mt * 32 + q16) * 32 + Ls) * 4 + rb;

    const int TF = T + F;
    float c1[2] = {0.f, 0.f}, c2[2] = {0.f, 0.f};
    int p = 0, q = 0;
    unsigned barno = 0;
    float a1M[2][4], a1C[2][4], a2M[2][4], a2C[2][4];

#define ZEROACC()                                                              \
    do {                                                                       \
        _Pragma("unroll")                                                      \
        for (int n = 0; n < 2; ++n)                                            \
            _Pragma("unroll")                                                  \
            for (int i = 0; i < 4; ++i)                                        \
                { a1M[n][i]=0.f; a1C[n][i]=0.f; a2M[n][i]=0.f; a2C[n][i]=0.f; } \
    } while (0)

// symmetric exchange: kh0 publishes layer-1 full partials, kh1 publishes
// layer-2 full; kh1 folds layer-1 into a1M, kh0 folds layer-2 into a2M.
// Executing warp's OWN correction (a1C / a2C) stays in regs and is added in
// the epilogues.
#define EXCHANGE()                                                             \
    do {                                                                       \
        if (kh == 0) {                                                         \
            s_kx[mt][lane][0] = make_float4(a1M[0][0]+a1C[0][0], a1M[0][1]+a1C[0][1], \
                                            a1M[0][2]+a1C[0][2], a1M[0][3]+a1C[0][3]); \
            s_kx[mt][lane][1] = make_float4(a1M[1][0]+a1C[1][0], a1M[1][1]+a1C[1][1], \
                                            a1M[1][2]+a1C[1][2], a1M[1][3]+a1C[1][3]); \
        } else {                                                               \
            s_kx[mt][lane][2] = make_float4(a2M[0][0]+a2C[0][0], a2M[0][1]+a2C[0][1], \
                                            a2M[0][2]+a2C[0][2], a2M[0][3]+a2C[0][3]); \
            s_kx[mt][lane][3] = make_float4(a2M[1][0]+a2C[1][0], a2M[1][1]+a2C[1][1], \
                                            a2M[1][2]+a2C[1][2], a2M[1][3]+a2C[1][3]); \
        }                                                                      \
        __syncthreads();                                                       \
        if (kh == 1) {                                                         \
            float4 e;                                                          \
            e = s_kx[mt][lane][0];                                             \
            a1M[0][0]+=e.x; a1M[0][1]+=e.y; a1M[0][2]+=e.z; a1M[0][3]+=e.w;    \
            e = s_kx[mt][lane][1];                                             \
            a1M[1][0]+=e.x; a1M[1][1]+=e.y; a1M[1][2]+=e.z; a1M[1][3]+=e.w;    \
        } else {                                                               \
            float4 e;                                                          \
            e = s_kx[mt][lane][2];                                             \
            a2M[0][0]+=e.x; a2M[0][1]+=e.y; a2M[0][2]+=e.z; a2M[0][3]+=e.w;    \
            e = s_kx[mt][lane][3];                                             \
            a2M[1][0]+=e.x; a2M[1][1]+=e.y; a2M[1][2]+=e.z; a2M[1][3]+=e.w;    \
        }                                                                      \
    } while (0)

#define PROJECT(bufq, tpos, feed)                                              \
    do {                                                                       \
        float part = __ldcg(g_h2p[bufq] + bid * HID + tid) * __ldg(Wout + tid);\
        _Pragma("unroll")                                                      \
        for (int sh = 16; sh; sh >>= 1)                                        \
            part += __shfl_xor_sync(0xffffffffu, part, sh);                    \
        if (lane == 0) s_red[wid] = part;                                      \
        __syncthreads();                                                       \
        if (tid == 0) {                                                        \
            float o = bo_out;                                                  \
            _Pragma("unroll")                                                  \
            for (int wq = 0; wq < 16; ++wq) o += s_red[wq];                    \
            out[bid * TF + (tpos)] = o;                                        \
            if (feed) __stcg(g_xfeed + bid, o);                                \
        }                                                                      \
        __syncthreads();                                                       \
    } while (0)

// layer-1 cell update (kh==1 warps): a1M = other-half full + own main;
// a1C = own correction (added here — full 3-term).
#define EPILOGUE1(xq0v, xq1v)                                                  \
    do {                                                                       \
        float xq[2] = { xq0v, xq1v };                                          \
        _Pragma("unroll")                                                      \
        for (int j = 0; j < 2; ++j) {                                          \
            float gi = a1M[0][j*2]   + a1C[0][j*2]   + b1g[0] + wxg[0] * xq[j];\
            float gf = a1M[0][j*2+1] + a1C[0][j*2+1] + b1g[1] + wxg[1] * xq[j];\
            float gg = a1M[1][j*2]   + a1C[1][j*2]   + b1g[2] + wxg[2] * xq[j];\
            float go = a1M[1][j*2+1] + a1C[1][j*2+1] + b1g[3] + wxg[3] * xq[j];\
            float ii = 1.f / (1.f + expf(-gi));                                \
            float ff = 1.f / (1.f + expf(-gf));                                \
            float g_ = tanhf(gg);                                              \
            float oo = 1.f / (1.f + expf(-go));                                \
            c1[j] = ff * c1[j] + ii * g_;                                      \
            float hv = oo * tanhf(c1[j]);                                      \
            __nv_bfloat16 bh = __float2bfloat16(hv);                           \
            __nv_bfloat16 bl = __float2bfloat16(hv - __bfloat162float(bh));    \
            st16g(g_h1h[p ^ 1], fidx + j, hf, bfbits(bh));                     \
            st16g(g_h1l[p ^ 1], fidx + j, hf, bfbits(bl));                     \
        }                                                                      \
    } while (0)

// layer-2 cell update (kh==0 warps): a2M = other-half full + own main; +a2C.
#define EPILOGUE2()                                                            \
    do {                                                                       \
        _Pragma("unroll")                                                      \
        for (int j = 0; j < 2; ++j) {                                          \
            float gi = a2M[0][j*2]   + a2C[0][j*2]   + b2g[0];                 \
            float gf = a2M[0][j*2+1] + a2C[0][j*2+1] + b2g[1];                 \
            float gg = a2M[1][j*2]   + a2C[1][j*2]   + b2g[2];                 \
            float go = a2M[1][j*2+1] + a2C[1][j*2+1] + b2g[3];                 \
            float ii = 1.f / (1.f + expf(-gi));                                \
            float ff = 1.f / (1.f + expf(-gf));                                \
            float g_ = tanhf(gg);                                              \
            float oo = 1.f / (1.f + expf(-go));                                \
            c2[j] = ff * c2[j] + ii * g_;                                      \
            float hv = oo * tanhf(c2[j]);                                      \
            __nv_bfloat16 bh = __float2bfloat16(hv);                           \
            __nv_bfloat16 bl = __float2bfloat16(hv - __bfloat162float(bh));    \
            st16g(g_h2h[q ^ 1], fidx + j, hf, bfbits(bh));                     \
            st16g(g_h2l[q ^ 1], fidx + j, hf, bfbits(bl));                     \
            __stcg(g_h2p[q ^ 1] + (j ? b1 : b0) * HID + kk, hv);               \
        }                                                                      \
    } while (0)

    // ================= sequence supersteps s = 0..T-1 ======================
    // superstep s: h1(s) [kh1 epilogue] and h2(s-1) [kh0 epilogue];
    // out(s-2) projected in the barrier-wait shadow.
    for (int s = 0; s < T; ++s) {
        const float* xsrc = g_xT + s * BAT;
        float xq0 = __ldcg(xsrc + b0);           // hidden under the GEMM
        float xq1 = __ldcg(xsrc + b1);

        ZEROACC();
        mma_fused3(a1M, a1C, a2M, a2C, wA, wH, wI,
                   g_h1h[p], g_h1l[p], g_h2h[q], g_h2l[q], lane, mt, kh);
        EXCHANGE();
        if (kh == 1) EPILOGUE1(xq0, xq1);
        else if (s > 0) EPILOGUE2();             // h2(s-1); zero at s=0
        barrier_arrive(++barno);
        if (s >= 2) PROJECT(q, s - 2, false);    // shadow work
        barrier_wait(barno);
        p ^= 1; q ^= 1;
    }

    // ================= feedback supersteps s = T..TF-1 =====================
    for (int s = T; s < TF; ++s) {
        ZEROACC();
        mma_fused3(a1M, a1C, a2M, a2C, wA, wH, wI,
                   g_h1h[p], g_h1l[p], g_h2h[q], g_h2l[q], lane, mt, kh);
        EXCHANGE();
        if (kh == 0) EPILOGUE2();                // h2(s-1)
        barrier_arrive(++barno);
        if (s == T) PROJECT(q, T - 2, false);    // straggler out(T-2), in shadow
        barrier_wait(barno);                     // h2(s-1) visible
        PROJECT(q ^ 1, s - 1, true);             // out(s-1) -> xfeed = x(s)
        barrier_arrive(++barno);
        barrier_wait(barno);                     // xfeed visible
        if (kh == 1) {
            EPILOGUE1(__ldcg(g_xfeed + b0), __ldcg(g_xfeed + b1));
        }
        barrier_arrive(++barno);
        barrier_wait(barno);                     // h1(s) visible
        p ^= 1; q ^= 1;
    }

    // ================= final superstep: layer 2 only for h2(TF-1) ==========
    ZEROACC();
    mma_fused3(a1M, a1C, a2M, a2C, wA, wH, wI,
               g_h1h[p], g_h1l[p], g_h2h[q], g_h2l[q], lane, mt, kh);
    EXCHANGE();
    if (kh == 0) EPILOGUE2();                    // h2(TF-1)
    barrier_arrive(++barno);
    barrier_wait(barno);
    PROJECT(q ^ 1, TF - 1, false);               // emit out(TF-1)

#undef ZEROACC
#undef EXCHANGE
#undef PROJECT
#undef EPILOGUE1
#undef EPILOGUE2
}

// ---------------------------------------------------------------------------
extern "C" void kernel_launch(void* const* d_in, const int* in_sizes, int n_in,
                              void* d_out, int out_size) {
    const float* x    = (const float*)d_in[0];
    const float* Wih1 = (const float*)d_in[2];
    const float* Whh1 = (const float*)d_in[3];
    const float* bih1 = (const float*)d_in[4];
    const float* bhh1 = (const float*)d_in[5];
    const float* Wih2 = (const float*)d_in[6];
    const float* Whh2 = (const float*)d_in[7];
    const float* bih2 = (const float*)d_in[8];
    const float* bhh2 = (const float*)d_in[9];
    const float* Wout = (const float*)d_in[10];
    const float* bout = (const float*)d_in[11];

    int T  = in_sizes[0] / BAT;       // 512
    int TF = out_size / BAT;          // 576
    int F  = TF - T;                  // 64

    const int smem = 24576 * 4;       // 98304 B dynamic (weights)

    cudaFuncSetAttribute(lstm_main, cudaFuncAttributeMaxDynamicSharedMemorySize, smem);

    reset_kernel<<<512, 256>>>(x, T);
    lstm_main<<<NCTA, NTHR, smem>>>(Wih1, Whh1, bih1, bhh1,
                                    Wih2, Whh2, bih2, bhh2,
                                    Wout, bout, (float*)d_out, T, F);
}